// round 4
// baseline (speedup 1.0000x reference)
#include <cuda_runtime.h>

#define N_SRC0 500000
#define N_DST0 100000
#define E0     1000000
#define N_DST1 10000
#define E1     100000
#define N_DST2 1024
#define E2     10240
#define D      128
#define NCLS   47

// ---------------- scratch (static device globals; no allocation) ----------------
__device__ float g_agg0[N_DST0 * D];
__device__ float g_h0  [N_DST0 * D];
__device__ float g_agg1[N_DST1 * D];
__device__ float g_h1  [N_DST1 * D];
__device__ float g_agg2[N_DST2 * D];
__device__ int   g_outdeg1[N_DST0];
__device__ int   g_indeg1 [N_DST1];
__device__ int   g_outdeg2[N_DST1];
__device__ int   g_indeg2 [N_DST2];

// ---------------- zero kernels ----------------
__global__ void zero_agg0_k() {
    int i = blockIdx.x * blockDim.x + threadIdx.x;
    if (i < N_DST0 * D / 4) ((float4*)g_agg0)[i] = make_float4(0.f, 0.f, 0.f, 0.f);
}

__global__ void zero_aux_k() {
    int i = blockIdx.x * blockDim.x + threadIdx.x;
    int stride = gridDim.x * blockDim.x;
    const int n1 = N_DST1 * D / 4;
    const int n2 = N_DST2 * D / 4;
    for (int j = i; j < n1 + n2; j += stride) {
        if (j < n1) ((float4*)g_agg1)[j] = make_float4(0.f, 0.f, 0.f, 0.f);
        else        ((float4*)g_agg2)[j - n1] = make_float4(0.f, 0.f, 0.f, 0.f);
    }
    const int ndeg = N_DST0 + N_DST1 + N_DST1 + N_DST2;
    for (int j = i; j < ndeg; j += stride) {
        if      (j < N_DST0)              g_outdeg1[j] = 0;
        else if (j < N_DST0 + N_DST1)     g_indeg1 [j - N_DST0] = 0;
        else if (j < N_DST0 + 2 * N_DST1) g_outdeg2[j - N_DST0 - N_DST1] = 0;
        else                              g_indeg2 [j - N_DST0 - 2 * N_DST1] = 0;
    }
}

// ---------------- degree counting (layers 1 & 2) ----------------
__global__ void deg_k(const int* __restrict__ s1, const int* __restrict__ d1,
                      const int* __restrict__ s2, const int* __restrict__ d2) {
    int t = blockIdx.x * blockDim.x + threadIdx.x;
    if (t < E1) {
        atomicAdd(&g_outdeg1[s1[t]], 1);
        atomicAdd(&g_indeg1 [d1[t]], 1);
    }
    if (t < E2) {
        atomicAdd(&g_outdeg2[s2[t]], 1);
        atomicAdd(&g_indeg2 [d2[t]], 1);
    }
}

// ---------------- edge scatter: one warp per 8 edges (MLP=8), vec4 reductions ----------------
__global__ void scatter_k(const float* __restrict__ feat, const int* __restrict__ src,
                          const int* __restrict__ dst, float* __restrict__ agg, int E) {
    int gt = blockIdx.x * blockDim.x + threadIdx.x;
    int warp = gt >> 5;
    int lane = gt & 31;
    int e0 = warp << 3;
    if (e0 >= E) return;
    int n = E - e0;
    float4 v[8];
    int dd[8];
#pragma unroll
    for (int j = 0; j < 8; j++) {
        if (j < n) {
            int s = __ldg(src + e0 + j);
            dd[j] = __ldg(dst + e0 + j);
            v[j] = __ldg(((const float4*)feat) + s * 32 + lane);
        }
    }
#pragma unroll
    for (int j = 0; j < 8; j++) {
        if (j < n) {
            float* p = agg + (long)dd[j] * D + (lane << 2);
            asm volatile("red.global.add.v4.f32 [%0], {%1,%2,%3,%4};"
                         :: "l"(p), "f"(v[j].x), "f"(v[j].y), "f"(v[j].z), "f"(v[j].w)
                         : "memory");
        }
    }
}

// ---------------- tf32 helpers ----------------
__device__ __forceinline__ float f2tf32(float x) {
    unsigned r;
    asm("cvt.rna.tf32.f32 %0, %1;" : "=r"(r) : "f"(x));
    return __uint_as_float(r);
}
__device__ __forceinline__ void tf32_split(float x, float& hi, float& lo) {
    hi = f2tf32(x);
    lo = f2tf32(x - hi);
}

#define MMA_TF32(C, A0, A1, A2, A3, B0, B1)                                   \
    asm volatile(                                                             \
        "mma.sync.aligned.m16n8k8.row.col.f32.tf32.tf32.f32 "                 \
        "{%0,%1,%2,%3},{%4,%5,%6,%7},{%8,%9},{%0,%1,%2,%3};"                  \
        : "+f"((C)[0]), "+f"((C)[1]), "+f"((C)[2]), "+f"((C)[3])              \
        : "r"(A0), "r"(A1), "r"(A2), "r"(A3), "r"(B0), "r"(B1))

// ---------------- 3xTF32 tensor-core GEMM: 64x128xK=128 tile, fused epilogue ----------------
// out[r] = relu( pre(r) * (A[rowmap(r)] @ W) + bias ) * post(r)
// A,W are split hi/lo in tf32; acc = hi*hi + hi*lo + lo*hi  (~fp32 accuracy)
__global__ __launch_bounds__(256) void gemm_k(
    const float* __restrict__ A, const float* __restrict__ W, const float* __restrict__ bias,
    const int* __restrict__ invp, const int* __restrict__ shufp,
    const int* __restrict__ pre_deg, const int* __restrict__ post_deg,
    float* __restrict__ out, int M)
{
    extern __shared__ float sm[];
    float* Wh = sm;                   // [128][132]  W^T hi:  Wh[n][k]
    float* Wl = sm + 128 * 132;       // [128][132]  W^T lo
    float* Ah = sm + 2 * 128 * 132;   // [64][132]   A tile hi
    float* Al = Ah + 64 * 132;        // [64][132]   A tile lo

    int t = threadIdx.x;
    int r0 = blockIdx.x * 64;

    // ---- load + transpose + split W
#pragma unroll
    for (int i = 0; i < 16; i++) {
        int lin = t + 256 * i;            // 4096 float4s
        int k = lin >> 5;
        int n0 = (lin & 31) * 4;
        float4 w = ((const float4*)W)[lin];
        float h, l;
        tf32_split(w.x, h, l); Wh[(n0 + 0) * 132 + k] = h; Wl[(n0 + 0) * 132 + k] = l;
        tf32_split(w.y, h, l); Wh[(n0 + 1) * 132 + k] = h; Wl[(n0 + 1) * 132 + k] = l;
        tf32_split(w.z, h, l); Wh[(n0 + 2) * 132 + k] = h; Wl[(n0 + 2) * 132 + k] = l;
        tf32_split(w.w, h, l); Wh[(n0 + 3) * 132 + k] = h; Wl[(n0 + 3) * 132 + k] = l;
    }
    // ---- load + split A tile rows (optional permutation gather): 64 rows x 32 float4
#pragma unroll
    for (int i = 0; i < 8; i++) {
        int lin = t + 256 * i;
        int m = lin >> 5;
        int kq = lin & 31;
        int r = r0 + m;
        float4 v = make_float4(0.f, 0.f, 0.f, 0.f);
        if (r < M) {
            int rs = r;
            if (invp) rs = invp[shufp[r]];
            v = ((const float4*)A)[rs * 32 + kq];
        }
        float4 vh, vl;
        tf32_split(v.x, vh.x, vl.x);
        tf32_split(v.y, vh.y, vl.y);
        tf32_split(v.z, vh.z, vl.z);
        tf32_split(v.w, vh.w, vl.w);
        *(float4*)&Ah[m * 132 + kq * 4] = vh;
        *(float4*)&Al[m * 132 + kq * 4] = vl;
    }
    __syncthreads();

    int lane = t & 31, wid = t >> 5;
    int g = lane >> 2, tg = lane & 3;
    int m_base = (wid & 1) << 5;     // 0 / 32
    int n_base = (wid >> 1) << 5;    // 0 / 32 / 64 / 96

    float c[2][4][4];
#pragma unroll
    for (int a = 0; a < 2; a++)
#pragma unroll
        for (int b = 0; b < 4; b++)
#pragma unroll
            for (int q = 0; q < 4; q++) c[a][b][q] = 0.f;

#pragma unroll
    for (int ks = 0; ks < 16; ks++) {
        int k0 = ks * 8;
        unsigned ah[2][4], al[2][4], bh[4][2], bl[4][2];
#pragma unroll
        for (int im = 0; im < 2; im++) {
            int off = (m_base + im * 16 + g) * 132 + k0 + tg;
            ah[im][0] = __float_as_uint(Ah[off]);
            ah[im][1] = __float_as_uint(Ah[off + 8 * 132]);
            ah[im][2] = __float_as_uint(Ah[off + 4]);
            ah[im][3] = __float_as_uint(Ah[off + 8 * 132 + 4]);
            al[im][0] = __float_as_uint(Al[off]);
            al[im][1] = __float_as_uint(Al[off + 8 * 132]);
            al[im][2] = __float_as_uint(Al[off + 4]);
            al[im][3] = __float_as_uint(Al[off + 8 * 132 + 4]);
        }
#pragma unroll
        for (int in_ = 0; in_ < 4; in_++) {
            int off = (n_base + in_ * 8 + g) * 132 + k0 + tg;
            bh[in_][0] = __float_as_uint(Wh[off]);
            bh[in_][1] = __float_as_uint(Wh[off + 4]);
            bl[in_][0] = __float_as_uint(Wl[off]);
            bl[in_][1] = __float_as_uint(Wl[off + 4]);
        }
#pragma unroll
        for (int im = 0; im < 2; im++)
#pragma unroll
            for (int in_ = 0; in_ < 4; in_++) {
                float* cc = c[im][in_];
                MMA_TF32(cc, al[im][0], al[im][1], al[im][2], al[im][3],
                         bh[in_][0], bh[in_][1]);
                MMA_TF32(cc, ah[im][0], ah[im][1], ah[im][2], ah[im][3],
                         bl[in_][0], bl[in_][1]);
                MMA_TF32(cc, ah[im][0], ah[im][1], ah[im][2], ah[im][3],
                         bh[in_][0], bh[in_][1]);
            }
    }

    // ---- epilogue: pre * acc + bias -> relu -> * post
#pragma unroll
    for (int im = 0; im < 2; im++) {
        int r_lo = r0 + m_base + im * 16 + g;
        int r_hi = r_lo + 8;
        float pre_lo = 1.f, pre_hi = 1.f, post_lo = 1.f, post_hi = 1.f;
        if (pre_deg) {
            if (r_lo < M) pre_lo = rsqrtf((float)max(pre_deg[r_lo], 1));
            if (r_hi < M) pre_hi = rsqrtf((float)max(pre_deg[r_hi], 1));
        }
        if (post_deg) {
            if (r_lo < M) post_lo = rsqrtf((float)max(post_deg[r_lo], 1));
            if (r_hi < M) post_hi = rsqrtf((float)max(post_deg[r_hi], 1));
        }
#pragma unroll
        for (int in_ = 0; in_ < 4; in_++) {
            int ccol = n_base + in_ * 8 + 2 * tg;
            float b0v = bias[ccol], b1v = bias[ccol + 1];
            if (r_lo < M) {
                float2 o;
                o.x = fmaxf(fmaf(c[im][in_][0], pre_lo, b0v), 0.f) * post_lo;
                o.y = fmaxf(fmaf(c[im][in_][1], pre_lo, b1v), 0.f) * post_lo;
                *(float2*)&out[(long)r_lo * 128 + ccol] = o;
            }
            if (r_hi < M) {
                float2 o;
                o.x = fmaxf(fmaf(c[im][in_][2], pre_hi, b0v), 0.f) * post_hi;
                o.y = fmaxf(fmaf(c[im][in_][3], pre_hi, b1v), 0.f) * post_hi;
                *(float2*)&out[(long)r_hi * 128 + ccol] = o;
            }
        }
    }
}

// ---------------- final small GEMM: [1024,128] @ [128,47] with indeg norm + bias ----------------
__global__ void gemm2_k(const float* __restrict__ agg2, const float* __restrict__ W2,
                        const float* __restrict__ b2, const int* __restrict__ indeg2,
                        float* __restrict__ out) {
    __shared__ float As[128];
    int row = blockIdx.x;
    int t = threadIdx.x;   // 64 threads
    As[t]      = agg2[row * 128 + t];
    As[t + 64] = agg2[row * 128 + t + 64];
    __syncthreads();
    if (t < NCLS) {
        float acc = 0.f;
#pragma unroll
        for (int k = 0; k < 128; k++) acc = fmaf(As[k], W2[k * NCLS + t], acc);
        float rs = rsqrtf((float)max(indeg2[row], 1));
        out[row * NCLS + t] = fmaf(acc, rs, b2[t]);
    }
}

// ---------------- launcher ----------------
extern "C" void kernel_launch(void* const* d_in, const int* in_sizes, int n_in,
                              void* d_out, int out_size) {
    const float* feats = (const float*)d_in[0];
    const int* src0 = (const int*)d_in[1];
    const int* dst0 = (const int*)d_in[2];
    const int* src1 = (const int*)d_in[3];
    const int* dst1 = (const int*)d_in[4];
    const int* src2 = (const int*)d_in[5];
    const int* dst2 = (const int*)d_in[6];
    const int* invp = (const int*)d_in[7];
    const int* shufp = (const int*)d_in[8];
    const float* W0 = (const float*)d_in[9];
    const float* b0 = (const float*)d_in[10];
    const float* W1 = (const float*)d_in[11];
    const float* b1 = (const float*)d_in[12];
    const float* W2 = (const float*)d_in[13];
    const float* b2 = (const float*)d_in[14];
    float* out = (float*)d_out;

    float *agg0, *h0, *agg1, *h1, *agg2;
    int *od1, *id1, *od2, *id2;
    cudaGetSymbolAddress((void**)&agg0, g_agg0);
    cudaGetSymbolAddress((void**)&h0,   g_h0);
    cudaGetSymbolAddress((void**)&agg1, g_agg1);
    cudaGetSymbolAddress((void**)&h1,   g_h1);
    cudaGetSymbolAddress((void**)&agg2, g_agg2);
    cudaGetSymbolAddress((void**)&od1,  g_outdeg1);
    cudaGetSymbolAddress((void**)&id1,  g_indeg1);
    cudaGetSymbolAddress((void**)&od2,  g_outdeg2);
    cudaGetSymbolAddress((void**)&id2,  g_indeg2);

    const int SMEM = (2 * 128 * 132 + 2 * 64 * 132) * 4;  // 202752 B
    cudaFuncSetAttribute(gemm_k, cudaFuncAttributeMaxDynamicSharedMemorySize, SMEM);

    // scatter grid: ceil((E/8) warps * 32 threads / 256)
#define SCATTER_BLOCKS(E) (((E) / 8 * 32 + 255) / 256)

    // zero scratch
    zero_agg0_k<<<(N_DST0 * D / 4 + 255) / 256, 256>>>();
    zero_aux_k<<<1378, 256>>>();
    // degrees for layers 1 & 2
    deg_k<<<(E1 + 255) / 256, 256>>>(src1, dst1, src2, dst2);

    // layer 0: aggregate raw feats (norm='none'), then GEMM + perm + bias + relu,
    // fold next layer's out-degree scaling.
    scatter_k<<<SCATTER_BLOCKS(E0), 256>>>(feats, src0, dst0, agg0, E0);
    gemm_k<<<(N_DST0 + 63) / 64, 256, SMEM>>>(agg0, W0, b0, invp, shufp,
                                              nullptr, od1, h0, N_DST0);

    // layer 1
    scatter_k<<<SCATTER_BLOCKS(E1), 256>>>(h0, src1, dst1, agg1, E1);
    gemm_k<<<(N_DST1 + 63) / 64, 256, SMEM>>>(agg1, W1, b1, nullptr, nullptr,
                                              id1, od2, h1, N_DST1);

    // layer 2
    scatter_k<<<SCATTER_BLOCKS(E2), 256>>>(h1, src2, dst2, agg2, E2);
    gemm2_k<<<N_DST2, 64>>>(agg2, W2, b2, id2, out);
}

// round 5
// speedup vs baseline: 1.2462x; 1.2462x over previous
#include <cuda_runtime.h>

#define N_SRC0 500000
#define N_DST0 100000
#define E0     1000000
#define N_DST1 10000
#define E1     100000
#define N_DST2 1024
#define E2     10240
#define D      128
#define NCLS   47

// ---------------- scratch (static device globals; no allocation) ----------------
__device__ float g_agg0[N_DST0 * D];
__device__ float g_h0  [N_DST0 * D];
__device__ float g_agg1[N_DST1 * D];
__device__ float g_h1  [N_DST1 * D];
__device__ float g_agg2[N_DST2 * D];
__device__ int   g_outdeg1[N_DST0];
__device__ int   g_indeg1 [N_DST1];
__device__ int   g_outdeg2[N_DST1];
__device__ int   g_indeg2 [N_DST2];
// precomputed W splits, transposed to [n][k] (n-major, k contiguous)
__device__ float g_W0h[D * D];
__device__ float g_W0l[D * D];
__device__ float g_W1h[D * D];
__device__ float g_W1l[D * D];

// ---------------- tf32 helpers ----------------
__device__ __forceinline__ float f2tf32(float x) {
    unsigned r;
    asm("cvt.rna.tf32.f32 %0, %1;" : "=r"(r) : "f"(x));
    return __uint_as_float(r);
}
__device__ __forceinline__ void tf32_split(float x, float& hi, float& lo) {
    hi = f2tf32(x);
    lo = f2tf32(x - hi);
}

// ---------------- W split+transpose (once) ----------------
__global__ void wsplit_k(const float* __restrict__ W0, const float* __restrict__ W1) {
    const float* W = (blockIdx.x == 0) ? W0 : W1;
    float* Wh = (blockIdx.x == 0) ? g_W0h : g_W1h;
    float* Wl = (blockIdx.x == 0) ? g_W0l : g_W1l;
    int t = threadIdx.x;   // 256 threads
#pragma unroll
    for (int i = 0; i < 64; i++) {
        int idx = t + 256 * i;          // 16384 elements
        int k = idx >> 7, n = idx & 127;
        float h, l;
        tf32_split(W[idx], h, l);
        Wh[n * D + k] = h;
        Wl[n * D + k] = l;
    }
}

// ---------------- zero kernels ----------------
__global__ void zero_agg0_k() {
    int i = blockIdx.x * blockDim.x + threadIdx.x;
    if (i < N_DST0 * D / 4) ((float4*)g_agg0)[i] = make_float4(0.f, 0.f, 0.f, 0.f);
}

__global__ void zero_aux_k() {
    int i = blockIdx.x * blockDim.x + threadIdx.x;
    int stride = gridDim.x * blockDim.x;
    const int n1 = N_DST1 * D / 4;
    const int n2 = N_DST2 * D / 4;
    for (int j = i; j < n1 + n2; j += stride) {
        if (j < n1) ((float4*)g_agg1)[j] = make_float4(0.f, 0.f, 0.f, 0.f);
        else        ((float4*)g_agg2)[j - n1] = make_float4(0.f, 0.f, 0.f, 0.f);
    }
    const int ndeg = N_DST0 + N_DST1 + N_DST1 + N_DST2;
    for (int j = i; j < ndeg; j += stride) {
        if      (j < N_DST0)              g_outdeg1[j] = 0;
        else if (j < N_DST0 + N_DST1)     g_indeg1 [j - N_DST0] = 0;
        else if (j < N_DST0 + 2 * N_DST1) g_outdeg2[j - N_DST0 - N_DST1] = 0;
        else                              g_indeg2 [j - N_DST0 - 2 * N_DST1] = 0;
    }
}

// ---------------- degree counting (layers 1 & 2) ----------------
__global__ void deg_k(const int* __restrict__ s1, const int* __restrict__ d1,
                      const int* __restrict__ s2, const int* __restrict__ d2) {
    int t = blockIdx.x * blockDim.x + threadIdx.x;
    if (t < E1) {
        atomicAdd(&g_outdeg1[s1[t]], 1);
        atomicAdd(&g_indeg1 [d1[t]], 1);
    }
    if (t < E2) {
        atomicAdd(&g_outdeg2[s2[t]], 1);
        atomicAdd(&g_indeg2 [d2[t]], 1);
    }
}

// ---------------- edge scatter: one warp per 8 edges (MLP=8), vec4 reductions ----------------
__global__ void scatter_k(const float* __restrict__ feat, const int* __restrict__ src,
                          const int* __restrict__ dst, float* __restrict__ agg, int E) {
    int gt = blockIdx.x * blockDim.x + threadIdx.x;
    int warp = gt >> 5;
    int lane = gt & 31;
    int e0 = warp << 3;
    if (e0 >= E) return;
    int n = E - e0;
    float4 v[8];
    int dd[8];
#pragma unroll
    for (int j = 0; j < 8; j++) {
        if (j < n) {
            int s = __ldg(src + e0 + j);
            dd[j] = __ldg(dst + e0 + j);
            v[j] = __ldg(((const float4*)feat) + s * 32 + lane);
        }
    }
#pragma unroll
    for (int j = 0; j < 8; j++) {
        if (j < n) {
            float* p = agg + (long)dd[j] * D + (lane << 2);
            asm volatile("red.global.add.v4.f32 [%0], {%1,%2,%3,%4};"
                         :: "l"(p), "f"(v[j].x), "f"(v[j].y), "f"(v[j].z), "f"(v[j].w)
                         : "memory");
        }
    }
}

#define MMA_TF32(C, A0, A1, A2, A3, B0, B1)                                   \
    asm volatile(                                                             \
        "mma.sync.aligned.m16n8k8.row.col.f32.tf32.tf32.f32 "                 \
        "{%0,%1,%2,%3},{%4,%5,%6,%7},{%8,%9},{%0,%1,%2,%3};"                  \
        : "+f"((C)[0]), "+f"((C)[1]), "+f"((C)[2]), "+f"((C)[3])              \
        : "r"(A0), "r"(A1), "r"(A2), "r"(A3), "r"(B0), "r"(B1))

// ---------------- 3xTF32 GEMM: 128x128 tile, 512 threads, K in 2 halves ----------------
// out[r] = relu( pre(r) * (A[rowmap(r)] @ W) + bias ) * post(r)
// Whg/Wlg are precomputed hi/lo splits of W, transposed [n][k].
__global__ __launch_bounds__(512) void gemm_k(
    const float* __restrict__ A,
    const float* __restrict__ Whg, const float* __restrict__ Wlg,
    const float* __restrict__ bias,
    const int* __restrict__ invp, const int* __restrict__ shufp,
    const int* __restrict__ pre_deg, const int* __restrict__ post_deg,
    float* __restrict__ out, int M)
{
    extern __shared__ float smd[];
    const int LD = 68;                 // 64 k + 4 pad
    float* Wh = smd;                   // [128][68]
    float* Wl = smd + 128 * LD;
    float* Ah = smd + 2 * 128 * LD;
    float* Al = smd + 3 * 128 * LD;
    __shared__ int rowmap[128];

    int t = threadIdx.x;
    int r0 = blockIdx.x * 128;

    if (t < 128) {
        int r = r0 + t;
        int rs = r;
        if (r < M && invp) rs = invp[shufp[r]];
        rowmap[t] = (r < M) ? rs : -1;
    }
    __syncthreads();

    int lane = t & 31, wid = t >> 5;
    int g = lane >> 2, tg = lane & 3;
    int m_base = (wid & 3) << 5;     // 0/32/64/96
    int n_base = (wid >> 2) << 5;    // 0/32/64/96

    float c[2][4][4];
#pragma unroll
    for (int a = 0; a < 2; a++)
#pragma unroll
        for (int b = 0; b < 4; b++)
#pragma unroll
            for (int q = 0; q < 4; q++) c[a][b][q] = 0.f;

#pragma unroll
    for (int half = 0; half < 2; half++) {
        int kof4 = half * 16;          // float4 offset of this k-half
        if (half) __syncthreads();     // protect smem reuse

        // ---- load W halves (coalesced, already split+transposed)
#pragma unroll
        for (int i = 0; i < 4; i++) {
            int lin = t + 512 * i;         // 2048 float4
            int n = lin >> 4, kq = lin & 15;
            ((float4*)&Wh[n * LD])[kq] = ((const float4*)Whg)[n * 32 + kof4 + kq];
            ((float4*)&Wl[n * LD])[kq] = ((const float4*)Wlg)[n * 32 + kof4 + kq];
        }
        // ---- load + split A half
#pragma unroll
        for (int i = 0; i < 4; i++) {
            int lin = t + 512 * i;         // 2048 float4
            int m = lin >> 4, kq = lin & 15;
            int rs = rowmap[m];
            float4 v = make_float4(0.f, 0.f, 0.f, 0.f);
            if (rs >= 0) v = ((const float4*)A)[rs * 32 + kof4 + kq];
            float4 vh, vl;
            tf32_split(v.x, vh.x, vl.x);
            tf32_split(v.y, vh.y, vl.y);
            tf32_split(v.z, vh.z, vl.z);
            tf32_split(v.w, vh.w, vl.w);
            ((float4*)&Ah[m * LD])[kq] = vh;
            ((float4*)&Al[m * LD])[kq] = vl;
        }
        __syncthreads();

#pragma unroll
        for (int ks = 0; ks < 8; ks++) {
            int k0 = ks * 8;
            unsigned ah[2][4], al[2][4], bh[4][2], bl[4][2];
#pragma unroll
            for (int im = 0; im < 2; im++) {
                int off = (m_base + im * 16 + g) * LD + k0 + tg;
                ah[im][0] = __float_as_uint(Ah[off]);
                ah[im][1] = __float_as_uint(Ah[off + 8 * LD]);
                ah[im][2] = __float_as_uint(Ah[off + 4]);
                ah[im][3] = __float_as_uint(Ah[off + 8 * LD + 4]);
                al[im][0] = __float_as_uint(Al[off]);
                al[im][1] = __float_as_uint(Al[off + 8 * LD]);
                al[im][2] = __float_as_uint(Al[off + 4]);
                al[im][3] = __float_as_uint(Al[off + 8 * LD + 4]);
            }
#pragma unroll
            for (int in_ = 0; in_ < 4; in_++) {
                int off = (n_base + in_ * 8 + g) * LD + k0 + tg;
                bh[in_][0] = __float_as_uint(Wh[off]);
                bh[in_][1] = __float_as_uint(Wh[off + 4]);
                bl[in_][0] = __float_as_uint(Wl[off]);
                bl[in_][1] = __float_as_uint(Wl[off + 4]);
            }
#pragma unroll
            for (int im = 0; im < 2; im++)
#pragma unroll
                for (int in_ = 0; in_ < 4; in_++) {
                    float* cc = c[im][in_];
                    MMA_TF32(cc, al[im][0], al[im][1], al[im][2], al[im][3],
                             bh[in_][0], bh[in_][1]);
                    MMA_TF32(cc, ah[im][0], ah[im][1], ah[im][2], ah[im][3],
                             bl[in_][0], bl[in_][1]);
                    MMA_TF32(cc, ah[im][0], ah[im][1], ah[im][2], ah[im][3],
                             bh[in_][0], bh[in_][1]);
                }
        }
    }

    // ---- epilogue: pre * acc + bias -> relu -> * post
#pragma unroll
    for (int im = 0; im < 2; im++) {
        int r_lo = r0 + m_base + im * 16 + g;
        int r_hi = r_lo + 8;
        float pre_lo = 1.f, pre_hi = 1.f, post_lo = 1.f, post_hi = 1.f;
        if (pre_deg) {
            if (r_lo < M) pre_lo = rsqrtf((float)max(pre_deg[r_lo], 1));
            if (r_hi < M) pre_hi = rsqrtf((float)max(pre_deg[r_hi], 1));
        }
        if (post_deg) {
            if (r_lo < M) post_lo = rsqrtf((float)max(post_deg[r_lo], 1));
            if (r_hi < M) post_hi = rsqrtf((float)max(post_deg[r_hi], 1));
        }
#pragma unroll
        for (int in_ = 0; in_ < 4; in_++) {
            int ccol = n_base + in_ * 8 + 2 * tg;
            float b0v = bias[ccol], b1v = bias[ccol + 1];
            if (r_lo < M) {
                float2 o;
                o.x = fmaxf(fmaf(c[im][in_][0], pre_lo, b0v), 0.f) * post_lo;
                o.y = fmaxf(fmaf(c[im][in_][1], pre_lo, b1v), 0.f) * post_lo;
                *(float2*)&out[(long)r_lo * 128 + ccol] = o;
            }
            if (r_hi < M) {
                float2 o;
                o.x = fmaxf(fmaf(c[im][in_][2], pre_hi, b0v), 0.f) * post_hi;
                o.y = fmaxf(fmaf(c[im][in_][3], pre_hi, b1v), 0.f) * post_hi;
                *(float2*)&out[(long)r_hi * 128 + ccol] = o;
            }
        }
    }
}

// ---------------- final small GEMM: [1024,128] @ [128,47] with indeg norm + bias ----------------
__global__ void gemm2_k(const float* __restrict__ agg2, const float* __restrict__ W2,
                        const float* __restrict__ b2, const int* __restrict__ indeg2,
                        float* __restrict__ out) {
    __shared__ float As[128];
    int row = blockIdx.x;
    int t = threadIdx.x;   // 64 threads
    As[t]      = agg2[row * 128 + t];
    As[t + 64] = agg2[row * 128 + t + 64];
    __syncthreads();
    if (t < NCLS) {
        float acc = 0.f;
#pragma unroll
        for (int k = 0; k < 128; k++) acc = fmaf(As[k], W2[k * NCLS + t], acc);
        float rs = rsqrtf((float)max(indeg2[row], 1));
        out[row * NCLS + t] = fmaf(acc, rs, b2[t]);
    }
}

// ---------------- launcher ----------------
extern "C" void kernel_launch(void* const* d_in, const int* in_sizes, int n_in,
                              void* d_out, int out_size) {
    const float* feats = (const float*)d_in[0];
    const int* src0 = (const int*)d_in[1];
    const int* dst0 = (const int*)d_in[2];
    const int* src1 = (const int*)d_in[3];
    const int* dst1 = (const int*)d_in[4];
    const int* src2 = (const int*)d_in[5];
    const int* dst2 = (const int*)d_in[6];
    const int* invp = (const int*)d_in[7];
    const int* shufp = (const int*)d_in[8];
    const float* W0 = (const float*)d_in[9];
    const float* b0 = (const float*)d_in[10];
    const float* W1 = (const float*)d_in[11];
    const float* b1 = (const float*)d_in[12];
    const float* W2 = (const float*)d_in[13];
    const float* b2 = (const float*)d_in[14];
    float* out = (float*)d_out;

    float *agg0, *h0, *agg1, *h1, *agg2;
    float *w0h, *w0l, *w1h, *w1l;
    int *od1, *id1, *od2, *id2;
    cudaGetSymbolAddress((void**)&agg0, g_agg0);
    cudaGetSymbolAddress((void**)&h0,   g_h0);
    cudaGetSymbolAddress((void**)&agg1, g_agg1);
    cudaGetSymbolAddress((void**)&h1,   g_h1);
    cudaGetSymbolAddress((void**)&agg2, g_agg2);
    cudaGetSymbolAddress((void**)&od1,  g_outdeg1);
    cudaGetSymbolAddress((void**)&id1,  g_indeg1);
    cudaGetSymbolAddress((void**)&od2,  g_outdeg2);
    cudaGetSymbolAddress((void**)&id2,  g_indeg2);
    cudaGetSymbolAddress((void**)&w0h,  g_W0h);
    cudaGetSymbolAddress((void**)&w0l,  g_W0l);
    cudaGetSymbolAddress((void**)&w1h,  g_W1h);
    cudaGetSymbolAddress((void**)&w1l,  g_W1l);

    const int SMEM = 4 * 128 * 68 * 4;  // 139264 B
    cudaFuncSetAttribute(gemm_k, cudaFuncAttributeMaxDynamicSharedMemorySize, SMEM);

#define SCATTER_BLOCKS(E) (((E) / 8 * 32 + 255) / 256)

    // prep: W splits, zero scratch, degrees
    wsplit_k<<<2, 256>>>(W0, W1);
    zero_agg0_k<<<(N_DST0 * D / 4 + 255) / 256, 256>>>();
    zero_aux_k<<<1378, 256>>>();
    deg_k<<<(E1 + 255) / 256, 256>>>(src1, dst1, src2, dst2);

    // layer 0
    scatter_k<<<SCATTER_BLOCKS(E0), 256>>>(feats, src0, dst0, agg0, E0);
    gemm_k<<<(N_DST0 + 127) / 128, 512, SMEM>>>(agg0, w0h, w0l, b0, invp, shufp,
                                                nullptr, od1, h0, N_DST0);

    // layer 1
    scatter_k<<<SCATTER_BLOCKS(E1), 256>>>(h0, src1, dst1, agg1, E1);
    gemm_k<<<(N_DST1 + 127) / 128, 512, SMEM>>>(agg1, w1h, w1l, b1, nullptr, nullptr,
                                                id1, od2, h1, N_DST1);

    // layer 2
    scatter_k<<<SCATTER_BLOCKS(E2), 256>>>(h1, src2, dst2, agg2, E2);
    gemm2_k<<<N_DST2, 64>>>(agg2, W2, b2, id2, out);
}

// round 6
// speedup vs baseline: 1.4909x; 1.1963x over previous
#include <cuda_runtime.h>
#include <cuda_bf16.h>

#define N_SRC0 500000
#define N_DST0 100000
#define E0     1000000
#define N_DST1 10000
#define E1     100000
#define N_DST2 1024
#define E2     10240
#define D      128
#define NCLS   47

// ---------------- scratch (static device globals; no allocation) ----------------
__device__ float g_agg0[N_DST0 * D];
__device__ float g_h0  [N_DST0 * D];
__device__ float g_agg1[N_DST1 * D];
__device__ float g_h1  [N_DST1 * D];
__device__ float g_agg2[N_DST2 * D];
__device__ int   g_outdeg1[N_DST0];
__device__ int   g_indeg1 [N_DST1];
__device__ int   g_outdeg2[N_DST1];
__device__ int   g_indeg2 [N_DST2];
// precomputed W bf16 hi/lo splits, transposed to [n][k] (n-major, k contiguous)
__device__ __nv_bfloat16 g_W0h[D * D];
__device__ __nv_bfloat16 g_W0l[D * D];
__device__ __nv_bfloat16 g_W1h[D * D];
__device__ __nv_bfloat16 g_W1l[D * D];

// ---------------- bf16 split helper ----------------
__device__ __forceinline__ void bsplit(float x, __nv_bfloat16& h, __nv_bfloat16& l) {
    h = __float2bfloat16_rn(x);
    l = __float2bfloat16_rn(x - __bfloat162float(h));
}

// ---------------- W split+transpose (once) ----------------
__global__ void wsplit_k(const float* __restrict__ W0, const float* __restrict__ W1) {
    const float* W = (blockIdx.x == 0) ? W0 : W1;
    __nv_bfloat16* Wh = (blockIdx.x == 0) ? g_W0h : g_W1h;
    __nv_bfloat16* Wl = (blockIdx.x == 0) ? g_W0l : g_W1l;
    int t = threadIdx.x;   // 256 threads
#pragma unroll
    for (int i = 0; i < 64; i++) {
        int idx = t + 256 * i;          // 16384 elements, W row-major [k][n]
        int k = idx >> 7, n = idx & 127;
        __nv_bfloat16 h, l;
        bsplit(W[idx], h, l);
        Wh[n * D + k] = h;
        Wl[n * D + k] = l;
    }
}

// ---------------- zero kernels ----------------
__global__ void zero_agg0_k() {
    int i = blockIdx.x * blockDim.x + threadIdx.x;
    if (i < N_DST0 * D / 4) ((float4*)g_agg0)[i] = make_float4(0.f, 0.f, 0.f, 0.f);
}

__global__ void zero_aux_k() {
    int i = blockIdx.x * blockDim.x + threadIdx.x;
    int stride = gridDim.x * blockDim.x;
    const int n1 = N_DST1 * D / 4;
    const int n2 = N_DST2 * D / 4;
    for (int j = i; j < n1 + n2; j += stride) {
        if (j < n1) ((float4*)g_agg1)[j] = make_float4(0.f, 0.f, 0.f, 0.f);
        else        ((float4*)g_agg2)[j - n1] = make_float4(0.f, 0.f, 0.f, 0.f);
    }
    const int ndeg = N_DST0 + N_DST1 + N_DST1 + N_DST2;
    for (int j = i; j < ndeg; j += stride) {
        if      (j < N_DST0)              g_outdeg1[j] = 0;
        else if (j < N_DST0 + N_DST1)     g_indeg1 [j - N_DST0] = 0;
        else if (j < N_DST0 + 2 * N_DST1) g_outdeg2[j - N_DST0 - N_DST1] = 0;
        else                              g_indeg2 [j - N_DST0 - 2 * N_DST1] = 0;
    }
}

// ---------------- degree counting (layers 1 & 2) ----------------
__global__ void deg_k(const int* __restrict__ s1, const int* __restrict__ d1,
                      const int* __restrict__ s2, const int* __restrict__ d2) {
    int t = blockIdx.x * blockDim.x + threadIdx.x;
    if (t < E1) {
        atomicAdd(&g_outdeg1[s1[t]], 1);
        atomicAdd(&g_indeg1 [d1[t]], 1);
    }
    if (t < E2) {
        atomicAdd(&g_outdeg2[s2[t]], 1);
        atomicAdd(&g_indeg2 [d2[t]], 1);
    }
}

// ---------------- edge scatter: one warp per 8 edges (MLP=8), vec4 reductions ----------------
__global__ void scatter_k(const float* __restrict__ feat, const int* __restrict__ src,
                          const int* __restrict__ dst, float* __restrict__ agg, int E) {
    int gt = blockIdx.x * blockDim.x + threadIdx.x;
    int warp = gt >> 5;
    int lane = gt & 31;
    int e0 = warp << 3;
    if (e0 >= E) return;
    int n = E - e0;
    float4 v[8];
    int dd[8];
#pragma unroll
    for (int j = 0; j < 8; j++) {
        if (j < n) {
            int s = __ldg(src + e0 + j);
            dd[j] = __ldg(dst + e0 + j);
            v[j] = __ldg(((const float4*)feat) + s * 32 + lane);
        }
    }
#pragma unroll
    for (int j = 0; j < 8; j++) {
        if (j < n) {
            float* p = agg + (long)dd[j] * D + (lane << 2);
            asm volatile("red.global.add.v4.f32 [%0], {%1,%2,%3,%4};"
                         :: "l"(p), "f"(v[j].x), "f"(v[j].y), "f"(v[j].z), "f"(v[j].w)
                         : "memory");
        }
    }
}

#define MMA_BF16(C, A0, A1, A2, A3, B0, B1)                                   \
    asm volatile(                                                             \
        "mma.sync.aligned.m16n8k16.row.col.f32.bf16.bf16.f32 "                \
        "{%0,%1,%2,%3},{%4,%5,%6,%7},{%8,%9},{%0,%1,%2,%3};"                  \
        : "+f"((C)[0]), "+f"((C)[1]), "+f"((C)[2]), "+f"((C)[3])              \
        : "r"(A0), "r"(A1), "r"(A2), "r"(A3), "r"(B0), "r"(B1))

// ---------------- 3xBF16 GEMM: 128x128 tile, 512 threads, full K=128 resident ----------------
// out[r] = relu( pre(r) * (A[rowmap(r)] @ W) + bias ) * post(r)
// Whg/Wlg: precomputed bf16 hi/lo splits of W, transposed [n][k].
// acc = Ah*Wh + Ah*Wl + Al*Wh  (residual ~2^-16 relative)
__global__ __launch_bounds__(512) void gemm_k(
    const float* __restrict__ A,
    const __nv_bfloat16* __restrict__ Whg, const __nv_bfloat16* __restrict__ Wlg,
    const float* __restrict__ bias,
    const int* __restrict__ invp, const int* __restrict__ shufp,
    const int* __restrict__ pre_deg, const int* __restrict__ post_deg,
    float* __restrict__ out, int M)
{
    extern __shared__ __nv_bfloat16 smb[];
    const int LD = 136;                       // 128 k + 8 pad (bf16 units)
    __nv_bfloat16* Wh = smb;                  // [128][136]
    __nv_bfloat16* Wl = smb + 128 * LD;
    __nv_bfloat16* Ah = smb + 2 * 128 * LD;
    __nv_bfloat16* Al = smb + 3 * 128 * LD;
    __shared__ int rowmap[128];

    int t = threadIdx.x;
    int r0 = blockIdx.x * 128;

    if (t < 128) {
        int r = r0 + t;
        int rs = r;
        if (r < M && invp) rs = invp[shufp[r]];
        rowmap[t] = (r < M) ? rs : -1;
    }
    __syncthreads();

    // ---- load W hi/lo (already split + transposed; 2048 uint4 each)
#pragma unroll
    for (int i = 0; i < 4; i++) {
        int lin = t + 512 * i;
        int n = lin >> 4, kq = lin & 15;      // kq: 8-bf16 chunk
        *(uint4*)(Wh + n * LD + kq * 8) = ((const uint4*)Whg)[lin];
        *(uint4*)(Wl + n * LD + kq * 8) = ((const uint4*)Wlg)[lin];
    }
    // ---- load + split A tile (4096 float4)
#pragma unroll
    for (int i = 0; i < 8; i++) {
        int lin = t + 512 * i;
        int m = lin >> 5, kq = lin & 31;      // kq: float4 index
        int rs = rowmap[m];
        float4 v = make_float4(0.f, 0.f, 0.f, 0.f);
        if (rs >= 0) v = ((const float4*)A)[rs * 32 + kq];
        __nv_bfloat16 h0, l0, h1, l1, h2, l2, h3, l3;
        bsplit(v.x, h0, l0); bsplit(v.y, h1, l1);
        bsplit(v.z, h2, l2); bsplit(v.w, h3, l3);
        __nv_bfloat162 ph01, ph23, pl01, pl23;
        ph01.x = h0; ph01.y = h1; ph23.x = h2; ph23.y = h3;
        pl01.x = l0; pl01.y = l1; pl23.x = l2; pl23.y = l3;
        uint2 uh, ul;
        uh.x = *(unsigned*)&ph01; uh.y = *(unsigned*)&ph23;
        ul.x = *(unsigned*)&pl01; ul.y = *(unsigned*)&pl23;
        *(uint2*)(Ah + m * LD + kq * 4) = uh;
        *(uint2*)(Al + m * LD + kq * 4) = ul;
    }
    __syncthreads();

    int lane = t & 31, wid = t >> 5;
    int g = lane >> 2, tg = lane & 3;
    int m_base = (wid & 3) << 5;     // 0/32/64/96
    int n_base = (wid >> 2) << 5;    // 0/32/64/96

    float c[2][4][4];
#pragma unroll
    for (int a = 0; a < 2; a++)
#pragma unroll
        for (int b = 0; b < 4; b++)
#pragma unroll
            for (int q = 0; q < 4; q++) c[a][b][q] = 0.f;

#pragma unroll
    for (int ks = 0; ks < 8; ks++) {
        int k0 = ks * 16;
        unsigned ah[2][4], al_[2][4], bh[4][2], bl[4][2];
#pragma unroll
        for (int im = 0; im < 2; im++) {
            int off = (m_base + im * 16 + g) * LD + k0 + 2 * tg;
            ah[im][0]  = *(const unsigned*)(Ah + off);
            ah[im][1]  = *(const unsigned*)(Ah + off + 8 * LD);
            ah[im][2]  = *(const unsigned*)(Ah + off + 8);
            ah[im][3]  = *(const unsigned*)(Ah + off + 8 * LD + 8);
            al_[im][0] = *(const unsigned*)(Al + off);
            al_[im][1] = *(const unsigned*)(Al + off + 8 * LD);
            al_[im][2] = *(const unsigned*)(Al + off + 8);
            al_[im][3] = *(const unsigned*)(Al + off + 8 * LD + 8);
        }
#pragma unroll
        for (int in_ = 0; in_ < 4; in_++) {
            int off = (n_base + in_ * 8 + g) * LD + k0 + 2 * tg;
            bh[in_][0] = *(const unsigned*)(Wh + off);
            bh[in_][1] = *(const unsigned*)(Wh + off + 8);
            bl[in_][0] = *(const unsigned*)(Wl + off);
            bl[in_][1] = *(const unsigned*)(Wl + off + 8);
        }
#pragma unroll
        for (int im = 0; im < 2; im++)
#pragma unroll
            for (int in_ = 0; in_ < 4; in_++) {
                float* cc = c[im][in_];
                MMA_BF16(cc, al_[im][0], al_[im][1], al_[im][2], al_[im][3],
                         bh[in_][0], bh[in_][1]);
                MMA_BF16(cc, ah[im][0], ah[im][1], ah[im][2], ah[im][3],
                         bl[in_][0], bl[in_][1]);
                MMA_BF16(cc, ah[im][0], ah[im][1], ah[im][2], ah[im][3],
                         bh[in_][0], bh[in_][1]);
            }
    }

    // ---- epilogue: pre * acc + bias -> relu -> * post
#pragma unroll
    for (int im = 0; im < 2; im++) {
        int r_lo = r0 + m_base + im * 16 + g;
        int r_hi = r_lo + 8;
        float pre_lo = 1.f, pre_hi = 1.f, post_lo = 1.f, post_hi = 1.f;
        if (pre_deg) {
            if (r_lo < M) pre_lo = rsqrtf((float)max(pre_deg[r_lo], 1));
            if (r_hi < M) pre_hi = rsqrtf((float)max(pre_deg[r_hi], 1));
        }
        if (post_deg) {
            if (r_lo < M) post_lo = rsqrtf((float)max(post_deg[r_lo], 1));
            if (r_hi < M) post_hi = rsqrtf((float)max(post_deg[r_hi], 1));
        }
#pragma unroll
        for (int in_ = 0; in_ < 4; in_++) {
            int ccol = n_base + in_ * 8 + 2 * tg;
            float b0v = bias[ccol], b1v = bias[ccol + 1];
            if (r_lo < M) {
                float2 o;
                o.x = fmaxf(fmaf(c[im][in_][0], pre_lo, b0v), 0.f) * post_lo;
                o.y = fmaxf(fmaf(c[im][in_][1], pre_lo, b1v), 0.f) * post_lo;
                *(float2*)&out[(long)r_lo * 128 + ccol] = o;
            }
            if (r_hi < M) {
                float2 o;
                o.x = fmaxf(fmaf(c[im][in_][2], pre_hi, b0v), 0.f) * post_hi;
                o.y = fmaxf(fmaf(c[im][in_][3], pre_hi, b1v), 0.f) * post_hi;
                *(float2*)&out[(long)r_hi * 128 + ccol] = o;
            }
        }
    }
}

// ---------------- final small GEMM: [1024,128] @ [128,47] with indeg norm + bias ----------------
__global__ void gemm2_k(const float* __restrict__ agg2, const float* __restrict__ W2,
                        const float* __restrict__ b2, const int* __restrict__ indeg2,
                        float* __restrict__ out) {
    __shared__ float As[128];
    int row = blockIdx.x;
    int t = threadIdx.x;   // 64 threads
    As[t]      = agg2[row * 128 + t];
    As[t + 64] = agg2[row * 128 + t + 64];
    __syncthreads();
    if (t < NCLS) {
        float acc = 0.f;
#pragma unroll
        for (int k = 0; k < 128; k++) acc = fmaf(As[k], W2[k * NCLS + t], acc);
        float rs = rsqrtf((float)max(indeg2[row], 1));
        out[row * NCLS + t] = fmaf(acc, rs, b2[t]);
    }
}

// ---------------- launcher ----------------
extern "C" void kernel_launch(void* const* d_in, const int* in_sizes, int n_in,
                              void* d_out, int out_size) {
    const float* feats = (const float*)d_in[0];
    const int* src0 = (const int*)d_in[1];
    const int* dst0 = (const int*)d_in[2];
    const int* src1 = (const int*)d_in[3];
    const int* dst1 = (const int*)d_in[4];
    const int* src2 = (const int*)d_in[5];
    const int* dst2 = (const int*)d_in[6];
    const int* invp = (const int*)d_in[7];
    const int* shufp = (const int*)d_in[8];
    const float* W0 = (const float*)d_in[9];
    const float* b0 = (const float*)d_in[10];
    const float* W1 = (const float*)d_in[11];
    const float* b1 = (const float*)d_in[12];
    const float* W2 = (const float*)d_in[13];
    const float* b2 = (const float*)d_in[14];
    float* out = (float*)d_out;

    float *agg0, *h0, *agg1, *h1, *agg2;
    __nv_bfloat16 *w0h, *w0l, *w1h, *w1l;
    int *od1, *id1, *od2, *id2;
    cudaGetSymbolAddress((void**)&agg0, g_agg0);
    cudaGetSymbolAddress((void**)&h0,   g_h0);
    cudaGetSymbolAddress((void**)&agg1, g_agg1);
    cudaGetSymbolAddress((void**)&h1,   g_h1);
    cudaGetSymbolAddress((void**)&agg2, g_agg2);
    cudaGetSymbolAddress((void**)&od1,  g_outdeg1);
    cudaGetSymbolAddress((void**)&id1,  g_indeg1);
    cudaGetSymbolAddress((void**)&od2,  g_outdeg2);
    cudaGetSymbolAddress((void**)&id2,  g_indeg2);
    cudaGetSymbolAddress((void**)&w0h,  g_W0h);
    cudaGetSymbolAddress((void**)&w0l,  g_W0l);
    cudaGetSymbolAddress((void**)&w1h,  g_W1h);
    cudaGetSymbolAddress((void**)&w1l,  g_W1l);

    const int SMEM = 4 * 128 * 136 * 2;  // 139264 B
    cudaFuncSetAttribute(gemm_k, cudaFuncAttributeMaxDynamicSharedMemorySize, SMEM);

    // side stream for prep work (fork/join; capture-legal)
    static cudaStream_t s1 = nullptr;
    static cudaEvent_t evFork = nullptr, evJoin = nullptr;
    if (!s1) {
        cudaStreamCreateWithFlags(&s1, cudaStreamNonBlocking);
        cudaEventCreateWithFlags(&evFork, cudaEventDisableTiming);
        cudaEventCreateWithFlags(&evJoin, cudaEventDisableTiming);
    }

#define SCATTER_BLOCKS(E) (((E) / 8 * 32 + 255) / 256)

    // fork: prep kernels (W splits, aux zero, degrees) run beside scatter0
    cudaEventRecord(evFork, 0);
    cudaStreamWaitEvent(s1, evFork, 0);
    wsplit_k<<<2, 256, 0, s1>>>(W0, W1);
    zero_aux_k<<<1378, 256, 0, s1>>>();
    deg_k<<<(E1 + 255) / 256, 256, 0, s1>>>(src1, dst1, src2, dst2);
    cudaEventRecord(evJoin, s1);

    // main: layer-0 aggregation path
    zero_agg0_k<<<(N_DST0 * D / 4 + 255) / 256, 256>>>();
    scatter_k<<<SCATTER_BLOCKS(E0), 256>>>(feats, src0, dst0, agg0, E0);

    // join before gemm0 (needs W splits + out-degrees + zeroed agg1/agg2)
    cudaStreamWaitEvent(0, evJoin, 0);

    gemm_k<<<(N_DST0 + 127) / 128, 512, SMEM>>>(agg0, w0h, w0l, b0, invp, shufp,
                                                nullptr, od1, h0, N_DST0);

    // layer 1
    scatter_k<<<SCATTER_BLOCKS(E1), 256>>>(h0, src1, dst1, agg1, E1);
    gemm_k<<<(N_DST1 + 127) / 128, 512, SMEM>>>(agg1, w1h, w1l, b1, nullptr, nullptr,
                                                id1, od2, h1, N_DST1);

    // layer 2
    scatter_k<<<SCATTER_BLOCKS(E2), 256>>>(h1, src2, dst2, agg2, E2);
    gemm2_k<<<N_DST2, 64>>>(agg2, W2, b2, id2, out);
}

// round 7
// speedup vs baseline: 1.6043x; 1.0761x over previous
#include <cuda_runtime.h>
#include <cuda_bf16.h>

#define N_SRC0 500000
#define N_DST0 100000
#define E0     1000000
#define N_DST1 10000
#define E1     100000
#define N_DST2 1024
#define E2     10240
#define D      128
#define NCLS   47

// padded bin layout for the fused 3-layer CSR build (pad each layer to 512)
#define PAD0 100352
#define PAD1 10240
#define PAD2 1024
#define TOTAL_BINS (PAD0 + PAD1 + PAD2)          // 111616
#define NSCAN_BLOCKS (TOTAL_BINS / 512)          // 218
#define E_TOTAL (E0 + E1 + E2)

// ---------------- scratch (static device globals; no allocation) ----------------
__device__ float g_agg0[N_DST0 * D];
__device__ float g_h0  [N_DST0 * D];
__device__ float g_agg1[N_DST1 * D];
__device__ float g_h1  [N_DST1 * D];
__device__ float g_agg2[N_DST2 * D];
__device__ int   g_outdeg1[N_DST0];
__device__ int   g_outdeg2[N_DST1];
__device__ int   g_cnt [TOTAL_BINS];       // per-bin histogram (also = in-degrees)
__device__ int   g_off [TOTAL_BINS + 1];   // exclusive offsets
__device__ int   g_pos [TOTAL_BINS];       // running cursors for bucket-place
__device__ int   g_bsum[NSCAN_BLOCKS];
__device__ int   g_esrc[E_TOTAL];          // src ids sorted by dst bin
// precomputed W bf16 hi/lo splits, transposed to [n][k]
__device__ __nv_bfloat16 g_W0h[D * D];
__device__ __nv_bfloat16 g_W0l[D * D];
__device__ __nv_bfloat16 g_W1h[D * D];
__device__ __nv_bfloat16 g_W1l[D * D];

// ---------------- bf16 split helper ----------------
__device__ __forceinline__ void bsplit(float x, __nv_bfloat16& h, __nv_bfloat16& l) {
    h = __float2bfloat16_rn(x);
    l = __float2bfloat16_rn(x - __bfloat162float(h));
}

// ---------------- W split+transpose (once) ----------------
__global__ void wsplit_k(const float* __restrict__ W0, const float* __restrict__ W1) {
    const float* W = (blockIdx.x == 0) ? W0 : W1;
    __nv_bfloat16* Wh = (blockIdx.x == 0) ? g_W0h : g_W1h;
    __nv_bfloat16* Wl = (blockIdx.x == 0) ? g_W0l : g_W1l;
    int t = threadIdx.x;
#pragma unroll
    for (int i = 0; i < 64; i++) {
        int idx = t + 256 * i;
        int k = idx >> 7, n = idx & 127;
        __nv_bfloat16 h, l;
        bsplit(W[idx], h, l);
        Wh[n * D + k] = h;
        Wl[n * D + k] = l;
    }
}

// ---------------- zero kernels ----------------
__global__ void zero_cnt_k() {
    int i = blockIdx.x * blockDim.x + threadIdx.x;
    if (i < TOTAL_BINS / 4) ((int4*)g_cnt)[i] = make_int4(0, 0, 0, 0);
}
__global__ void zero_od_k() {
    int i = blockIdx.x * blockDim.x + threadIdx.x;
    if (i < N_DST0) g_outdeg1[i] = 0;
    if (i < N_DST1) g_outdeg2[i] = 0;
}

// ---------------- src-side degree counting ----------------
__global__ void deg_src_k(const int* __restrict__ s1, const int* __restrict__ s2) {
    int t = blockIdx.x * blockDim.x + threadIdx.x;
    if (t < E1) atomicAdd(&g_outdeg1[s1[t]], 1);
    if (t < E2) atomicAdd(&g_outdeg2[s2[t]], 1);
}

// ---------------- CSR build: histogram, 3-kernel scan, bucket place ----------------
__global__ void hist_k(const int* __restrict__ d0, const int* __restrict__ d1,
                       const int* __restrict__ d2) {
    int t = blockIdx.x * blockDim.x + threadIdx.x;
    if (t < E0) atomicAdd(&g_cnt[d0[t]], 1);
    if (t < E1) atomicAdd(&g_cnt[PAD0 + d1[t]], 1);
    if (t < E2) atomicAdd(&g_cnt[PAD0 + PAD1 + d2[t]], 1);
}

__global__ void scanA_k() {
    __shared__ int s[512];
    int b = blockIdx.x, t = threadIdx.x, i = b * 512 + t;
    int v = g_cnt[i];
    s[t] = v; __syncthreads();
#pragma unroll
    for (int o = 1; o < 512; o <<= 1) {
        int x = (t >= o) ? s[t - o] : 0;
        __syncthreads();
        s[t] += x;
        __syncthreads();
    }
    g_off[i] = s[t];                 // block-local inclusive
    if (t == 511) g_bsum[b] = s[511];
}

__global__ void scanB_k() {
    __shared__ int s[256];
    int t = threadIdx.x;
    int v = (t < NSCAN_BLOCKS) ? g_bsum[t] : 0;
    s[t] = v; __syncthreads();
#pragma unroll
    for (int o = 1; o < 256; o <<= 1) {
        int x = (t >= o) ? s[t - o] : 0;
        __syncthreads();
        s[t] += x;
        __syncthreads();
    }
    if (t < NSCAN_BLOCKS) g_bsum[t] = s[t] - v;      // exclusive block offsets
    if (t == NSCAN_BLOCKS - 1) g_off[TOTAL_BINS] = s[t];   // grand total
}

__global__ void scanC_k() {
    int b = blockIdx.x, t = threadIdx.x, i = b * 512 + t;
    int excl = g_off[i] - g_cnt[i] + g_bsum[b];
    g_off[i] = excl;
    g_pos[i] = excl;
}

__global__ void build_k(const int* __restrict__ s0, const int* __restrict__ d0,
                        const int* __restrict__ s1, const int* __restrict__ d1,
                        const int* __restrict__ s2, const int* __restrict__ d2) {
    int t = blockIdx.x * blockDim.x + threadIdx.x;
    if (t < E0) { int p = atomicAdd(&g_pos[d0[t]], 1);               g_esrc[p] = s0[t]; }
    if (t < E1) { int p = atomicAdd(&g_pos[PAD0 + d1[t]], 1);        g_esrc[p] = s1[t]; }
    if (t < E2) { int p = atomicAdd(&g_pos[PAD0 + PAD1 + d2[t]], 1); g_esrc[p] = s2[t]; }
}

// ---------------- CSR gather-aggregate: one warp per dst bin, no atomics ----------------
__global__ void gather_k(const float* __restrict__ feat, float* __restrict__ agg,
                         int binbase, int nbins) {
    int gt = blockIdx.x * blockDim.x + threadIdx.x;
    int w = gt >> 5, lane = gt & 31;
    if (w >= nbins) return;
    int beg = g_off[binbase + w];
    int end = g_off[binbase + w + 1];
    float4 acc = make_float4(0.f, 0.f, 0.f, 0.f);
    int i = beg;
    for (; i + 4 <= end; i += 4) {
        int s0 = __ldg(g_esrc + i);
        int s1 = __ldg(g_esrc + i + 1);
        int s2 = __ldg(g_esrc + i + 2);
        int s3 = __ldg(g_esrc + i + 3);
        float4 v0 = __ldg((const float4*)feat + s0 * 32 + lane);
        float4 v1 = __ldg((const float4*)feat + s1 * 32 + lane);
        float4 v2 = __ldg((const float4*)feat + s2 * 32 + lane);
        float4 v3 = __ldg((const float4*)feat + s3 * 32 + lane);
        acc.x += v0.x + v1.x; acc.y += v0.y + v1.y;
        acc.z += v0.z + v1.z; acc.w += v0.w + v1.w;
        acc.x += v2.x + v3.x; acc.y += v2.y + v3.y;
        acc.z += v2.z + v3.z; acc.w += v2.w + v3.w;
    }
    for (; i < end; i++) {
        int s = __ldg(g_esrc + i);
        float4 v = __ldg((const float4*)feat + s * 32 + lane);
        acc.x += v.x; acc.y += v.y; acc.z += v.z; acc.w += v.w;
    }
    ((float4*)agg)[w * 32 + lane] = acc;
}

#define MMA_BF16(C, A0, A1, A2, A3, B0, B1)                                   \
    asm volatile(                                                             \
        "mma.sync.aligned.m16n8k16.row.col.f32.bf16.bf16.f32 "                \
        "{%0,%1,%2,%3},{%4,%5,%6,%7},{%8,%9},{%0,%1,%2,%3};"                  \
        : "+f"((C)[0]), "+f"((C)[1]), "+f"((C)[2]), "+f"((C)[3])              \
        : "r"(A0), "r"(A1), "r"(A2), "r"(A3), "r"(B0), "r"(B1))

// ---------------- 3xBF16 GEMM: 128x128 tile, 512 threads, full K=128 resident ----------------
__global__ __launch_bounds__(512) void gemm_k(
    const float* __restrict__ A,
    const __nv_bfloat16* __restrict__ Whg, const __nv_bfloat16* __restrict__ Wlg,
    const float* __restrict__ bias,
    const int* __restrict__ invp, const int* __restrict__ shufp,
    const int* __restrict__ pre_deg, const int* __restrict__ post_deg,
    float* __restrict__ out, int M)
{
    extern __shared__ __nv_bfloat16 smb[];
    const int LD = 136;
    __nv_bfloat16* Wh = smb;
    __nv_bfloat16* Wl = smb + 128 * LD;
    __nv_bfloat16* Ah = smb + 2 * 128 * LD;
    __nv_bfloat16* Al = smb + 3 * 128 * LD;
    __shared__ int rowmap[128];

    int t = threadIdx.x;
    int r0 = blockIdx.x * 128;

    if (t < 128) {
        int r = r0 + t;
        int rs = r;
        if (r < M && invp) rs = invp[shufp[r]];
        rowmap[t] = (r < M) ? rs : -1;
    }
    __syncthreads();

#pragma unroll
    for (int i = 0; i < 4; i++) {
        int lin = t + 512 * i;
        int n = lin >> 4, kq = lin & 15;
        *(uint4*)(Wh + n * LD + kq * 8) = ((const uint4*)Whg)[lin];
        *(uint4*)(Wl + n * LD + kq * 8) = ((const uint4*)Wlg)[lin];
    }
#pragma unroll
    for (int i = 0; i < 8; i++) {
        int lin = t + 512 * i;
        int m = lin >> 5, kq = lin & 31;
        int rs = rowmap[m];
        float4 v = make_float4(0.f, 0.f, 0.f, 0.f);
        if (rs >= 0) v = ((const float4*)A)[rs * 32 + kq];
        __nv_bfloat16 h0, l0, h1, l1, h2, l2, h3, l3;
        bsplit(v.x, h0, l0); bsplit(v.y, h1, l1);
        bsplit(v.z, h2, l2); bsplit(v.w, h3, l3);
        __nv_bfloat162 ph01, ph23, pl01, pl23;
        ph01.x = h0; ph01.y = h1; ph23.x = h2; ph23.y = h3;
        pl01.x = l0; pl01.y = l1; pl23.x = l2; pl23.y = l3;
        uint2 uh, ul;
        uh.x = *(unsigned*)&ph01; uh.y = *(unsigned*)&ph23;
        ul.x = *(unsigned*)&pl01; ul.y = *(unsigned*)&pl23;
        *(uint2*)(Ah + m * LD + kq * 4) = uh;
        *(uint2*)(Al + m * LD + kq * 4) = ul;
    }
    __syncthreads();

    int lane = t & 31, wid = t >> 5;
    int g = lane >> 2, tg = lane & 3;
    int m_base = (wid & 3) << 5;
    int n_base = (wid >> 2) << 5;

    float c[2][4][4];
#pragma unroll
    for (int a = 0; a < 2; a++)
#pragma unroll
        for (int b = 0; b < 4; b++)
#pragma unroll
            for (int q = 0; q < 4; q++) c[a][b][q] = 0.f;

#pragma unroll
    for (int ks = 0; ks < 8; ks++) {
        int k0 = ks * 16;
        unsigned ah[2][4], al_[2][4], bh[4][2], bl[4][2];
#pragma unroll
        for (int im = 0; im < 2; im++) {
            int off = (m_base + im * 16 + g) * LD + k0 + 2 * tg;
            ah[im][0]  = *(const unsigned*)(Ah + off);
            ah[im][1]  = *(const unsigned*)(Ah + off + 8 * LD);
            ah[im][2]  = *(const unsigned*)(Ah + off + 8);
            ah[im][3]  = *(const unsigned*)(Ah + off + 8 * LD + 8);
            al_[im][0] = *(const unsigned*)(Al + off);
            al_[im][1] = *(const unsigned*)(Al + off + 8 * LD);
            al_[im][2] = *(const unsigned*)(Al + off + 8);
            al_[im][3] = *(const unsigned*)(Al + off + 8 * LD + 8);
        }
#pragma unroll
        for (int in_ = 0; in_ < 4; in_++) {
            int off = (n_base + in_ * 8 + g) * LD + k0 + 2 * tg;
            bh[in_][0] = *(const unsigned*)(Wh + off);
            bh[in_][1] = *(const unsigned*)(Wh + off + 8);
            bl[in_][0] = *(const unsigned*)(Wl + off);
            bl[in_][1] = *(const unsigned*)(Wl + off + 8);
        }
#pragma unroll
        for (int im = 0; im < 2; im++)
#pragma unroll
            for (int in_ = 0; in_ < 4; in_++) {
                float* cc = c[im][in_];
                MMA_BF16(cc, al_[im][0], al_[im][1], al_[im][2], al_[im][3],
                         bh[in_][0], bh[in_][1]);
                MMA_BF16(cc, ah[im][0], ah[im][1], ah[im][2], ah[im][3],
                         bl[in_][0], bl[in_][1]);
                MMA_BF16(cc, ah[im][0], ah[im][1], ah[im][2], ah[im][3],
                         bh[in_][0], bh[in_][1]);
            }
    }

#pragma unroll
    for (int im = 0; im < 2; im++) {
        int r_lo = r0 + m_base + im * 16 + g;
        int r_hi = r_lo + 8;
        float pre_lo = 1.f, pre_hi = 1.f, post_lo = 1.f, post_hi = 1.f;
        if (pre_deg) {
            if (r_lo < M) pre_lo = rsqrtf((float)max(pre_deg[r_lo], 1));
            if (r_hi < M) pre_hi = rsqrtf((float)max(pre_deg[r_hi], 1));
        }
        if (post_deg) {
            if (r_lo < M) post_lo = rsqrtf((float)max(post_deg[r_lo], 1));
            if (r_hi < M) post_hi = rsqrtf((float)max(post_deg[r_hi], 1));
        }
#pragma unroll
        for (int in_ = 0; in_ < 4; in_++) {
            int ccol = n_base + in_ * 8 + 2 * tg;
            float b0v = bias[ccol], b1v = bias[ccol + 1];
            if (r_lo < M) {
                float2 o;
                o.x = fmaxf(fmaf(c[im][in_][0], pre_lo, b0v), 0.f) * post_lo;
                o.y = fmaxf(fmaf(c[im][in_][1], pre_lo, b1v), 0.f) * post_lo;
                *(float2*)&out[(long)r_lo * 128 + ccol] = o;
            }
            if (r_hi < M) {
                float2 o;
                o.x = fmaxf(fmaf(c[im][in_][2], pre_hi, b0v), 0.f) * post_hi;
                o.y = fmaxf(fmaf(c[im][in_][3], pre_hi, b1v), 0.f) * post_hi;
                *(float2*)&out[(long)r_hi * 128 + ccol] = o;
            }
        }
    }
}

// ---------------- final small GEMM: [1024,128] @ [128,47] with indeg norm + bias ----------------
__global__ void gemm2_k(const float* __restrict__ agg2, const float* __restrict__ W2,
                        const float* __restrict__ b2, const int* __restrict__ indeg2,
                        float* __restrict__ out) {
    __shared__ float As[128];
    int row = blockIdx.x;
    int t = threadIdx.x;   // 64 threads
    As[t]      = agg2[row * 128 + t];
    As[t + 64] = agg2[row * 128 + t + 64];
    __syncthreads();
    if (t < NCLS) {
        float acc = 0.f;
#pragma unroll
        for (int k = 0; k < 128; k++) acc = fmaf(As[k], W2[k * NCLS + t], acc);
        float rs = rsqrtf((float)max(indeg2[row], 1));
        out[row * NCLS + t] = fmaf(acc, rs, b2[t]);
    }
}

// ---------------- launcher ----------------
extern "C" void kernel_launch(void* const* d_in, const int* in_sizes, int n_in,
                              void* d_out, int out_size) {
    const float* feats = (const float*)d_in[0];
    const int* src0 = (const int*)d_in[1];
    const int* dst0 = (const int*)d_in[2];
    const int* src1 = (const int*)d_in[3];
    const int* dst1 = (const int*)d_in[4];
    const int* src2 = (const int*)d_in[5];
    const int* dst2 = (const int*)d_in[6];
    const int* invp = (const int*)d_in[7];
    const int* shufp = (const int*)d_in[8];
    const float* W0 = (const float*)d_in[9];
    const float* b0 = (const float*)d_in[10];
    const float* W1 = (const float*)d_in[11];
    const float* b1 = (const float*)d_in[12];
    const float* W2 = (const float*)d_in[13];
    const float* b2 = (const float*)d_in[14];
    float* out = (float*)d_out;

    float *agg0, *h0, *agg1, *h1, *agg2;
    __nv_bfloat16 *w0h, *w0l, *w1h, *w1l;
    int *od1, *od2, *cnt;
    cudaGetSymbolAddress((void**)&agg0, g_agg0);
    cudaGetSymbolAddress((void**)&h0,   g_h0);
    cudaGetSymbolAddress((void**)&agg1, g_agg1);
    cudaGetSymbolAddress((void**)&h1,   g_h1);
    cudaGetSymbolAddress((void**)&agg2, g_agg2);
    cudaGetSymbolAddress((void**)&od1,  g_outdeg1);
    cudaGetSymbolAddress((void**)&od2,  g_outdeg2);
    cudaGetSymbolAddress((void**)&cnt,  g_cnt);
    cudaGetSymbolAddress((void**)&w0h,  g_W0h);
    cudaGetSymbolAddress((void**)&w0l,  g_W0l);
    cudaGetSymbolAddress((void**)&w1h,  g_W1h);
    cudaGetSymbolAddress((void**)&w1l,  g_W1l);
    int* indeg1 = cnt + PAD0;
    int* indeg2 = cnt + PAD0 + PAD1;

    const int SMEM = 4 * 128 * 136 * 2;  // 139264 B
    cudaFuncSetAttribute(gemm_k, cudaFuncAttributeMaxDynamicSharedMemorySize, SMEM);

    static cudaStream_t s1 = nullptr;
    static cudaEvent_t evFork = nullptr, evJoin = nullptr;
    if (!s1) {
        cudaStreamCreateWithFlags(&s1, cudaStreamNonBlocking);
        cudaEventCreateWithFlags(&evFork, cudaEventDisableTiming);
        cudaEventCreateWithFlags(&evJoin, cudaEventDisableTiming);
    }

    // fork: side stream does W splits + src-degree work (needed only by gemm0)
    cudaEventRecord(evFork, 0);
    cudaStreamWaitEvent(s1, evFork, 0);
    wsplit_k<<<2, 256, 0, s1>>>(W0, W1);
    zero_od_k<<<(N_DST0 + 255) / 256, 256, 0, s1>>>();
    deg_src_k<<<(E1 + 255) / 256, 256, 0, s1>>>(src1, src2);
    cudaEventRecord(evJoin, s1);

    // main: CSR build for all 3 layers, then layer-0 gather
    zero_cnt_k<<<(TOTAL_BINS / 4 + 255) / 256, 256>>>();
    hist_k<<<(E0 + 255) / 256, 256>>>(dst0, dst1, dst2);
    scanA_k<<<NSCAN_BLOCKS, 512>>>();
    scanB_k<<<1, 256>>>();
    scanC_k<<<NSCAN_BLOCKS, 512>>>();
    build_k<<<(E0 + 255) / 256, 256>>>(src0, dst0, src1, dst1, src2, dst2);

    gather_k<<<(N_DST0 * 32 + 255) / 256, 256>>>(feats, agg0, 0, N_DST0);

    // join before gemm0 (needs W splits + out-degrees)
    cudaStreamWaitEvent(0, evJoin, 0);

    gemm_k<<<(N_DST0 + 127) / 128, 512, SMEM>>>(agg0, w0h, w0l, b0, invp, shufp,
                                                nullptr, od1, h0, N_DST0);

    // layer 1
    gather_k<<<(N_DST1 * 32 + 255) / 256, 256>>>(h0, agg1, PAD0, N_DST1);
    gemm_k<<<(N_DST1 + 127) / 128, 512, SMEM>>>(agg1, w1h, w1l, b1, nullptr, nullptr,
                                                indeg1, od2, h1, N_DST1);

    // layer 2
    gather_k<<<(N_DST2 * 32 + 255) / 256, 256>>>(h1, agg2, PAD0 + PAD1, N_DST2);
    gemm2_k<<<N_DST2, 64>>>(agg2, W2, b2, indeg2, out);
}